// round 8
// baseline (speedup 1.0000x reference)
#include <cuda_runtime.h>
#include <cuda_bf16.h>
#include <math.h>
#include <stdint.h>

typedef __nv_bfloat16 bf16;

#define N_SRC1 200000
#define N_TGT1 50000
#define N_TGT2 10000
#define F_IN   256
#define F_HID  192
#define F_OUT  128
#define E1_MAX 1000000
#define E2_MAX 300000

// ---------------- scratch ----------------
__device__ bf16 g_m1_hi[N_TGT1 * F_IN];
__device__ bf16 g_m1_lo[N_TGT1 * F_IN];
__device__ float g_h1[(size_t)N_TGT1 * F_HID];
__device__ bf16 g_h1_hi[N_TGT2 * F_HID];
__device__ bf16 g_h1_lo[N_TGT2 * F_HID];
__device__ bf16 g_m2_hi[N_TGT2 * F_HID];
__device__ bf16 g_m2_lo[N_TGT2 * F_HID];
__device__ bf16 g_h2_hi[N_TGT2 * F_HID];
__device__ bf16 g_h2_lo[N_TGT2 * F_HID];
__device__ bf16 g_er_hi[N_TGT2 * F_HID];
__device__ bf16 g_er_lo[N_TGT2 * F_HID];
__device__ float g_logits[N_TGT2 * F_OUT];
// weight hi/lo planes
__device__ bf16 g_wl1_hi[F_HID * F_IN],  g_wl1_lo[F_HID * F_IN];
__device__ bf16 g_wr1_hi[F_HID * F_IN],  g_wr1_lo[F_HID * F_IN];
__device__ bf16 g_wl2_hi[F_HID * F_HID], g_wl2_lo[F_HID * F_HID];
__device__ bf16 g_wr2_hi[F_HID * F_HID], g_wr2_lo[F_HID * F_HID];
__device__ bf16 g_w1_hi[F_HID * F_HID],  g_w1_lo[F_HID * F_HID];
__device__ bf16 g_w2_hi[F_OUT * F_HID],  g_w2_lo[F_OUT * F_HID];
// CSR
__device__ int g_cnt1[N_TGT1];
__device__ int g_cnt2[N_TGT2];
__device__ int g_bsum1[1024];
__device__ int g_bsum2[1024];
__device__ int g_offs1[N_TGT1 + 1];
__device__ int g_offs2[N_TGT2 + 1];
__device__ int g_csr1[E1_MAX];
__device__ int g_csr2[E2_MAX];

// ---------------- CSR build ----------------
__global__ void hist_kernel(const int* __restrict__ tgt, int E, int* __restrict__ cnt) {
    int i = blockIdx.x * blockDim.x + threadIdx.x;
    if (i < E) atomicAdd(&cnt[tgt[i]], 1);
}

#define SCAN_B 256
__global__ void block_sum_kernel(const int* __restrict__ cnt, int n, int* __restrict__ bsum) {
    __shared__ int sm[SCAN_B];
    int t = threadIdx.x;
    int i = blockIdx.x * SCAN_B + t;
    sm[t] = (i < n) ? cnt[i] : 0;
    __syncthreads();
    for (int off = SCAN_B / 2; off > 0; off >>= 1) {
        if (t < off) sm[t] += sm[t + off];
        __syncthreads();
    }
    if (t == 0) bsum[blockIdx.x] = sm[0];
}

// single-block (256 threads) exclusive scan via shfl; handles G <= 1024 (4 per thread)
__global__ void scan_bsum_kernel(int* __restrict__ bsum, int G, int* __restrict__ total) {
    __shared__ int warp_sums[8];
    int t = threadIdx.x;
    int lane = t & 31, warp = t >> 5;
    int v[4];
    int base = t * 4;
#pragma unroll
    for (int q = 0; q < 4; q++) v[q] = (base + q < G) ? bsum[base + q] : 0;
    int mysum = v[0] + v[1] + v[2] + v[3];
    int run = mysum;
#pragma unroll
    for (int off = 1; off < 32; off <<= 1) {
        int u = __shfl_up_sync(0xffffffffu, run, off);
        if (lane >= off) run += u;
    }
    if (lane == 31) warp_sums[warp] = run;
    __syncthreads();
    int wpre = 0;
#pragma unroll
    for (int w = 0; w < 8; w++) {
        int ws = warp_sums[w];
        if (w < warp) wpre += ws;
    }
    int excl = wpre + run - mysum;
#pragma unroll
    for (int q = 0; q < 4; q++) {
        if (base + q < G) bsum[base + q] = excl;
        excl += v[q];
    }
    if (t == 255) *total = wpre + run;
}

// per-block exclusive scan + block prefix -> offs; also seeds cursor[i] = offs[i]
__global__ void scatter_offs_kernel(const int* __restrict__ cnt, int n,
                                    const int* __restrict__ bsum,
                                    int* __restrict__ offs, int* __restrict__ cursor) {
    __shared__ int sm[SCAN_B];
    int t = threadIdx.x;
    int i = blockIdx.x * SCAN_B + t;
    int v = (i < n) ? cnt[i] : 0;
    sm[t] = v;
    __syncthreads();
    for (int off = 1; off < SCAN_B; off <<= 1) {
        int u = (t >= off) ? sm[t - off] : 0;
        __syncthreads();
        sm[t] += u;
        __syncthreads();
    }
    if (i < n) {
        int o = bsum[blockIdx.x] + sm[t] - v;
        offs[i] = o;
        cursor[i] = o;
    }
}

// cursor pre-seeded with offsets: single atomic gives final position
__global__ void fill_kernel(const int* __restrict__ src, const int* __restrict__ tgt, int E,
                            int* __restrict__ cursor, int* __restrict__ csr) {
    int i = blockIdx.x * blockDim.x + threadIdx.x;
    if (i < E) {
        int p = atomicAdd(&cursor[tgt[i]], 1);
        csr[p] = src[i];
    }
}

// ---------------- splits ----------------
__device__ __forceinline__ void split2(float v, bf16& h, bf16& l) {
    bf16 hh = __float2bfloat16_rn(v);
    h = hh;
    l = __float2bfloat16_rn(v - __bfloat162float(hh));
}

__global__ void split_weights_kernel(const float* __restrict__ wl1, const float* __restrict__ wr1,
                                     const float* __restrict__ wl2, const float* __restrict__ wr2,
                                     const float* __restrict__ w1,  const float* __restrict__ w2) {
    int i = blockIdx.x * 256 + threadIdx.x;
    const int A = F_HID * F_IN;
    const int B = F_HID * F_HID;
    const int C = F_OUT * F_HID;
    float v; bf16 *hp, *lp; int o;
    if      (i < A)             { o = i;               v = wl1[o]; hp = g_wl1_hi; lp = g_wl1_lo; }
    else if (i < 2*A)           { o = i - A;           v = wr1[o]; hp = g_wr1_hi; lp = g_wr1_lo; }
    else if (i < 2*A + B)       { o = i - 2*A;         v = wl2[o]; hp = g_wl2_hi; lp = g_wl2_lo; }
    else if (i < 2*A + 2*B)     { o = i - 2*A - B;     v = wr2[o]; hp = g_wr2_hi; lp = g_wr2_lo; }
    else if (i < 2*A + 3*B)     { o = i - 2*A - 2*B;   v = w1[o];  hp = g_w1_hi;  lp = g_w1_lo; }
    else if (i < 2*A + 3*B + C) { o = i - 2*A - 3*B;   v = w2[o];  hp = g_w2_hi;  lp = g_w2_lo; }
    else return;
    bf16 h, l; split2(v, h, l);
    hp[o] = h; lp[o] = l;
}

// streaming 16-bit store (evict-first: don't pollute L2)
__device__ __forceinline__ void stcs_u16(bf16* p, bf16 v) {
    unsigned short s = *reinterpret_cast<unsigned short*>(&v);
    asm volatile("st.global.cs.u16 [%0], %1;" :: "l"(p), "h"(s) : "memory");
}

// ---------------- segment mean -> hi/lo planes ----------------
template <int F, bool STREAM_OUT>
__global__ void aggregate_hilo(const float* __restrict__ X, const int* __restrict__ csr,
                               const int* __restrict__ offs,
                               bf16* __restrict__ hi, bf16* __restrict__ lo) {
    int node = blockIdx.x;
    int t = threadIdx.x;
    int s = offs[node], e = offs[node + 1];
    float acc = 0.0f;
    int j = s;
    for (; j + 7 < e; j += 8) {
        int idx[8];
#pragma unroll
        for (int q = 0; q < 8; q++) idx[q] = __ldg(&csr[j + q]);
        float v[8];
#pragma unroll
        for (int q = 0; q < 8; q++) v[q] = X[(size_t)idx[q] * F + t];
        acc += ((v[0] + v[1]) + (v[2] + v[3])) + ((v[4] + v[5]) + (v[6] + v[7]));
    }
    for (; j < e; j++) acc += X[(size_t)__ldg(&csr[j]) * F + t];
    int deg = e - s;
    float m = acc * (1.0f / (float)(deg > 1 ? deg : 1));
    bf16 h, l; split2(m, h, l);
    size_t o = (size_t)node * F + t;
    if (STREAM_OUT) {
        stcs_u16(hi + o, h);
        stcs_u16(lo + o, l);
    } else {
        hi[o] = h; lo[o] = l;
    }
}

// ---------------- bf16x3 tensor-core GEMM (register double-buffered) ----------------
#define BM 128
#define BN 64
#define BKT 32
#define SLDA 40

__device__ __forceinline__ void ldsm4(uint32_t r[4], uint32_t addr) {
    asm volatile("ldmatrix.sync.aligned.m8n8.x4.shared.b16 {%0,%1,%2,%3}, [%4];"
                 : "=r"(r[0]), "=r"(r[1]), "=r"(r[2]), "=r"(r[3]) : "r"(addr));
}
__device__ __forceinline__ void mma_bf16(float d[4], const uint32_t a[4], uint32_t b0, uint32_t b1) {
    asm volatile("mma.sync.aligned.m16n8k16.row.col.f32.bf16.bf16.f32 "
                 "{%0,%1,%2,%3},{%4,%5,%6,%7},{%8,%9},{%0,%1,%2,%3};"
                 : "+f"(d[0]), "+f"(d[1]), "+f"(d[2]), "+f"(d[3])
                 : "r"(a[0]), "r"(a[1]), "r"(a[2]), "r"(a[3]), "r"(b0), "r"(b1));
}

__device__ __forceinline__ void split8(const float f[8], uint4& h, uint4& l) {
    __nv_bfloat162 hh[4], ll[4];
#pragma unroll
    for (int i = 0; i < 4; i++) {
        bf16 h0, l0, h1, l1;
        split2(f[2 * i], h0, l0);
        split2(f[2 * i + 1], h1, l1);
        hh[i].x = h0; hh[i].y = h1;
        ll[i].x = l0; ll[i].y = l1;
    }
    h = *(uint4*)hh;
    l = *(uint4*)ll;
}

template <int K, bool F32SRC>
__device__ __forceinline__ void mma_phase(const void* __restrict__ Ahi_v, const bf16* __restrict__ Alo,
                                          const bf16* __restrict__ Whi, const bf16* __restrict__ Wlo,
                                          int M, int m0, int n0,
                                          bf16 (*sA)[SLDA], bf16 (*sW)[SLDA],
                                          float acc[2][4][4]) {
    int t = threadIdx.x;
    int lane = t & 31, warp = t >> 5;
    int wm = (warp & 3) * 32, wn = (warp >> 2) * 32;
    uint32_t sA_u = (uint32_t)__cvta_generic_to_shared(&sA[0][0]);
    uint32_t sW_u = (uint32_t)__cvta_generic_to_shared(&sW[0][0]);

    const int ar = t >> 1, ac = (t & 1) * 16;
    const int wr = t >> 2, wc = (t & 3) * 8;

    uint32_t a_off[2][2], b_off[2][2];
#pragma unroll
    for (int p = 0; p < 2; p++) {
#pragma unroll
        for (int mf = 0; mf < 2; mf++)
            a_off[p][mf] = sA_u + (uint32_t)(((p * BM + wm + mf * 16 + (lane & 15)) * SLDA + ((lane >> 4) * 8)) * 2);
#pragma unroll
        for (int np = 0; np < 2; np++)
            b_off[p][np] = sW_u + (uint32_t)(((p * BN + wn + np * 16 + (lane & 7) + ((lane >> 4) * 8)) * SLDA +
                                             (((lane >> 3) & 1) * 8)) * 2);
    }

    const bool av = (m0 + ar) < M;
    uint4 sh0, sh1, sl0, sl1, swh, swl;

    auto fetch = [&](int kt) {
        if (F32SRC) {
            const float* Xf = (const float*)Ahi_v;
            float f[16];
            if (av) {
                size_t abase = (size_t)(m0 + ar) * K + kt + ac;
#pragma unroll
                for (int q = 0; q < 4; q++)
                    *(float4*)&f[4 * q] = *(const float4*)(Xf + abase + 4 * q);
            } else {
#pragma unroll
                for (int q = 0; q < 16; q++) f[q] = 0.f;
            }
            split8(&f[0], sh0, sl0);
            split8(&f[8], sh1, sl1);
        } else {
            const bf16* Ahi = (const bf16*)Ahi_v;
            uint4 z = make_uint4(0, 0, 0, 0);
            size_t abase = (size_t)(m0 + ar) * K + kt + ac;
            sh0 = av ? *(const uint4*)(Ahi + abase)     : z;
            sh1 = av ? *(const uint4*)(Ahi + abase + 8) : z;
            sl0 = av ? *(const uint4*)(Alo + abase)     : z;
            sl1 = av ? *(const uint4*)(Alo + abase + 8) : z;
        }
        size_t wbase = (size_t)(n0 + wr) * K + kt + wc;
        swh = *(const uint4*)(Whi + wbase);
        swl = *(const uint4*)(Wlo + wbase);
    };

    fetch(0);
    for (int kt = 0; kt < K; kt += BKT) {
        __syncthreads();
        *(uint4*)&sA[ar][ac]          = sh0;
        *(uint4*)&sA[ar][ac + 8]      = sh1;
        *(uint4*)&sA[BM + ar][ac]     = sl0;
        *(uint4*)&sA[BM + ar][ac + 8] = sl1;
        *(uint4*)&sW[wr][wc]      = swh;
        *(uint4*)&sW[BN + wr][wc] = swl;
        __syncthreads();
        if (kt + BKT < K) fetch(kt + BKT);
#pragma unroll
        for (int ks = 0; ks < 2; ks++) {
            uint32_t a[2][2][4], b[2][2][4];
#pragma unroll
            for (int p = 0; p < 2; p++) {
#pragma unroll
                for (int mf = 0; mf < 2; mf++) ldsm4(a[p][mf], a_off[p][mf] + ks * 32);
#pragma unroll
                for (int np = 0; np < 2; np++) ldsm4(b[p][np], b_off[p][np] + ks * 32);
            }
#pragma unroll
            for (int mf = 0; mf < 2; mf++)
#pragma unroll
                for (int nf = 0; nf < 4; nf++) {
                    uint32_t bh0 = b[0][nf >> 1][(nf & 1) * 2], bh1 = b[0][nf >> 1][(nf & 1) * 2 + 1];
                    uint32_t bl0 = b[1][nf >> 1][(nf & 1) * 2], bl1 = b[1][nf >> 1][(nf & 1) * 2 + 1];
                    mma_bf16(acc[mf][nf], a[0][mf], bh0, bh1);
                    mma_bf16(acc[mf][nf], a[0][mf], bl0, bl1);
                    mma_bf16(acc[mf][nf], a[1][mf], bh0, bh1);
                }
        }
    }
}

template <int K1, int K2, bool A2F32, bool WF32, bool F32RELU, bool WHILO>
__global__ __launch_bounds__(256, 2) void gemm_mma(
    const bf16* __restrict__ A1hi, const bf16* __restrict__ A1lo,
    const void* __restrict__ A2hi, const bf16* __restrict__ A2lo,
    const bf16* __restrict__ W1hi, const bf16* __restrict__ W1lo,
    const bf16* __restrict__ W2hi, const bf16* __restrict__ W2lo,
    const float* __restrict__ bias,
    float* __restrict__ C, bf16* __restrict__ Ohi, bf16* __restrict__ Olo,
    int M, int N, int hilo_limit) {
    __shared__ bf16 sA[2 * BM][SLDA];
    __shared__ bf16 sW[2 * BN][SLDA];
    float acc[2][4][4];
#pragma unroll
    for (int i = 0; i < 2; i++)
#pragma unroll
        for (int j = 0; j < 4; j++)
#pragma unroll
            for (int k = 0; k < 4; k++) acc[i][j][k] = 0.f;

    int m0 = blockIdx.x * BM, n0 = blockIdx.y * BN;

    mma_phase<K1, false>(A1hi, A1lo, W1hi, W1lo, M, m0, n0, sA, sW, acc);
    if constexpr (K2 > 0)
        mma_phase<K2, A2F32>(A2hi, A2lo, W2hi, W2lo, M, m0, n0, sA, sW, acc);

    int t = threadIdx.x, lane = t & 31, warp = t >> 5;
    int wm = (warp & 3) * 32, wn = (warp >> 2) * 32;
#pragma unroll
    for (int mf = 0; mf < 2; mf++) {
        int row0 = m0 + wm + mf * 16 + (lane >> 2);
        int row1 = row0 + 8;
#pragma unroll
        for (int nf = 0; nf < 4; nf++) {
            int col = n0 + wn + nf * 8 + (lane & 3) * 2;
            float b0 = bias[col], b1 = bias[col + 1];
            float v00 = acc[mf][nf][0] + b0, v01 = acc[mf][nf][1] + b1;
            float v10 = acc[mf][nf][2] + b0, v11 = acc[mf][nf][3] + b1;
#pragma unroll
            for (int half = 0; half < 2; half++) {
                int row = half ? row1 : row0;
                float a0 = half ? v10 : v00;
                float a1 = half ? v11 : v01;
                if (row < M) {
                    if (WF32) {
                        float o0 = F32RELU ? fmaxf(a0, 0.f) : a0;
                        float o1 = F32RELU ? fmaxf(a1, 0.f) : a1;
                        *(float2*)&C[(size_t)row * N + col] = make_float2(o0, o1);
                    }
                    if (WHILO && row < hilo_limit) {
                        float r0 = fmaxf(a0, 0.f), r1 = fmaxf(a1, 0.f);
                        bf16 h0, l0, h1, l1;
                        split2(r0, h0, l0); split2(r1, h1, l1);
                        __nv_bfloat162 hv; hv.x = h0; hv.y = h1;
                        __nv_bfloat162 lv; lv.x = l0; lv.y = l1;
                        *(__nv_bfloat162*)&Ohi[(size_t)row * N + col] = hv;
                        *(__nv_bfloat162*)&Olo[(size_t)row * N + col] = lv;
                    }
                }
            }
        }
    }
}

// ---------------- log_softmax ----------------
__global__ void logsoftmax_kernel(const float* __restrict__ logits, float* __restrict__ out) {
    __shared__ float red[128];
    int row = blockIdx.x;
    int t = threadIdx.x;
    float v = logits[row * F_OUT + t];
    red[t] = v;
    __syncthreads();
    for (int off = 64; off > 0; off >>= 1) {
        if (t < off) red[t] = fmaxf(red[t], red[t + off]);
        __syncthreads();
    }
    float mx = red[0];
    __syncthreads();
    red[t] = expf(v - mx);
    __syncthreads();
    for (int off = 64; off > 0; off >>= 1) {
        if (t < off) red[t] += red[t + off];
        __syncthreads();
    }
    float lse = logf(red[0]);
    out[row * F_OUT + t] = v - mx - lse;
}

// ---------------- launch (single stream, graph-capture safe) ----------------
extern "C" void kernel_launch(void* const* d_in, const int* in_sizes, int n_in,
                              void* d_out, int out_size) {
    const float* x   = (const float*)d_in[0];
    const int*   ei1 = (const int*)d_in[1];
    const int*   ei2 = (const int*)d_in[2];
    const float* Wl1 = (const float*)d_in[3];
    const float* bl1 = (const float*)d_in[4];
    const float* Wr1 = (const float*)d_in[5];
    const float* Wl2 = (const float*)d_in[6];
    const float* bl2 = (const float*)d_in[7];
    const float* Wr2 = (const float*)d_in[8];
    const float* W1  = (const float*)d_in[9];
    const float* b1  = (const float*)d_in[10];
    const float* W2  = (const float*)d_in[11];
    const float* b2  = (const float*)d_in[12];

    int E1 = in_sizes[1] / 2;
    int E2 = in_sizes[2] / 2;
    const int* src1 = ei1;
    const int* tgt1 = ei1 + E1;
    const int* src2 = ei2;
    const int* tgt2 = ei2 + E2;

    float* out_ls  = (float*)d_out;
    float* out_emb = (float*)d_out + N_TGT2 * F_OUT;

    bf16 *p_m1hi, *p_m1lo, *p_h1hi, *p_h1lo, *p_m2hi, *p_m2lo;
    bf16 *p_h2hi, *p_h2lo, *p_erhi, *p_erlo;
    bf16 *p_wl1h, *p_wl1l, *p_wr1h, *p_wr1l, *p_wl2h, *p_wl2l, *p_wr2h, *p_wr2l;
    bf16 *p_w1h, *p_w1l, *p_w2h, *p_w2l;
    float *p_h1, *p_logits;
    int *p_cnt1, *p_cnt2, *p_bsum1, *p_bsum2, *p_offs1, *p_offs2, *p_csr1, *p_csr2;
    cudaGetSymbolAddress((void**)&p_m1hi, g_m1_hi); cudaGetSymbolAddress((void**)&p_m1lo, g_m1_lo);
    cudaGetSymbolAddress((void**)&p_h1hi, g_h1_hi); cudaGetSymbolAddress((void**)&p_h1lo, g_h1_lo);
    cudaGetSymbolAddress((void**)&p_m2hi, g_m2_hi); cudaGetSymbolAddress((void**)&p_m2lo, g_m2_lo);
    cudaGetSymbolAddress((void**)&p_h2hi, g_h2_hi); cudaGetSymbolAddress((void**)&p_h2lo, g_h2_lo);
    cudaGetSymbolAddress((void**)&p_erhi, g_er_hi); cudaGetSymbolAddress((void**)&p_erlo, g_er_lo);
    cudaGetSymbolAddress((void**)&p_wl1h, g_wl1_hi); cudaGetSymbolAddress((void**)&p_wl1l, g_wl1_lo);
    cudaGetSymbolAddress((void**)&p_wr1h, g_wr1_hi); cudaGetSymbolAddress((void**)&p_wr1l, g_wr1_lo);
    cudaGetSymbolAddress((void**)&p_wl2h, g_wl2_hi); cudaGetSymbolAddress((void**)&p_wl2l, g_wl2_lo);
    cudaGetSymbolAddress((void**)&p_wr2h, g_wr2_hi); cudaGetSymbolAddress((void**)&p_wr2l, g_wr2_lo);
    cudaGetSymbolAddress((void**)&p_w1h,  g_w1_hi);  cudaGetSymbolAddress((void**)&p_w1l,  g_w1_lo);
    cudaGetSymbolAddress((void**)&p_w2h,  g_w2_hi);  cudaGetSymbolAddress((void**)&p_w2l,  g_w2_lo);
    cudaGetSymbolAddress((void**)&p_h1,     g_h1);
    cudaGetSymbolAddress((void**)&p_logits, g_logits);
    cudaGetSymbolAddress((void**)&p_cnt1,  g_cnt1);
    cudaGetSymbolAddress((void**)&p_cnt2,  g_cnt2);
    cudaGetSymbolAddress((void**)&p_bsum1, g_bsum1);
    cudaGetSymbolAddress((void**)&p_bsum2, g_bsum2);
    cudaGetSymbolAddress((void**)&p_offs1, g_offs1);
    cudaGetSymbolAddress((void**)&p_offs2, g_offs2);
    cudaGetSymbolAddress((void**)&p_csr1,  g_csr1);
    cudaGetSymbolAddress((void**)&p_csr2,  g_csr2);

    const int G1 = (N_TGT1 + SCAN_B - 1) / SCAN_B;
    const int G2 = (N_TGT2 + SCAN_B - 1) / SCAN_B;

    // weight splits
    {
        const int total = 2 * (F_HID * F_IN) + 3 * (F_HID * F_HID) + F_OUT * F_HID;
        split_weights_kernel<<<(total + 255) / 256, 256>>>(Wl1, Wr1, Wl2, Wr2, W1, W2);
    }

    // ---- layer 1 CSR ----
    cudaMemsetAsync(p_cnt1, 0, N_TGT1 * sizeof(int));
    hist_kernel<<<(E1 + 255) / 256, 256>>>(tgt1, E1, p_cnt1);
    block_sum_kernel<<<G1, SCAN_B>>>(p_cnt1, N_TGT1, p_bsum1);
    scan_bsum_kernel<<<1, 256>>>(p_bsum1, G1, p_offs1 + N_TGT1);
    scatter_offs_kernel<<<G1, SCAN_B>>>(p_cnt1, N_TGT1, p_bsum1, p_offs1, p_cnt1);
    fill_kernel<<<(E1 + 255) / 256, 256>>>(src1, tgt1, E1, p_cnt1, p_csr1);
    aggregate_hilo<F_IN, true><<<N_TGT1, F_IN>>>(x, p_csr1, p_offs1, p_m1hi, p_m1lo);

    // h1 = relu(mean1 @ Wl1^T + x[:50k] @ Wr1^T + bl1)
    gemm_mma<F_IN, F_IN, true, true, true, true>
        <<<dim3((N_TGT1 + BM - 1) / BM, F_HID / BN), 256>>>(
            p_m1hi, p_m1lo, x, nullptr, p_wl1h, p_wl1l, p_wr1h, p_wr1l,
            bl1, p_h1, p_h1hi, p_h1lo, N_TGT1, F_HID, N_TGT2);

    // ---- layer 2 CSR ----
    cudaMemsetAsync(p_cnt2, 0, N_TGT2 * sizeof(int));
    hist_kernel<<<(E2 + 255) / 256, 256>>>(tgt2, E2, p_cnt2);
    block_sum_kernel<<<G2, SCAN_B>>>(p_cnt2, N_TGT2, p_bsum2);
    scan_bsum_kernel<<<1, 256>>>(p_bsum2, G2, p_offs2 + N_TGT2);
    scatter_offs_kernel<<<G2, SCAN_B>>>(p_cnt2, N_TGT2, p_bsum2, p_offs2, p_cnt2);
    fill_kernel<<<(E2 + 255) / 256, 256>>>(src2, tgt2, E2, p_cnt2, p_csr2);
    aggregate_hilo<F_HID, false><<<N_TGT2, F_HID>>>(p_h1, p_csr2, p_offs2, p_m2hi, p_m2lo);

    // h2 = relu(mean2 @ Wl2^T + h1[:10k] @ Wr2^T + bl2)
    gemm_mma<F_HID, F_HID, false, false, false, true>
        <<<dim3((N_TGT2 + BM - 1) / BM, F_HID / BN), 256>>>(
            p_m2hi, p_m2lo, p_h1hi, p_h1lo, p_wl2h, p_wl2l, p_wr2h, p_wr2l,
            bl2, nullptr, p_h2hi, p_h2lo, N_TGT2, F_HID, N_TGT2);

    // embedding = h2 @ W1^T + b1
    gemm_mma<F_HID, 0, false, true, false, true>
        <<<dim3((N_TGT2 + BM - 1) / BM, F_HID / BN), 256>>>(
            p_h2hi, p_h2lo, nullptr, nullptr, p_w1h, p_w1l, nullptr, nullptr,
            b1, out_emb, p_erhi, p_erlo, N_TGT2, F_HID, N_TGT2);

    // logits = relu(emb) @ W2^T + b2
    gemm_mma<F_HID, 0, false, true, false, false>
        <<<dim3((N_TGT2 + BM - 1) / BM, F_OUT / BN), 256>>>(
            p_erhi, p_erlo, nullptr, nullptr, p_w2h, p_w2l, nullptr, nullptr,
            b2, p_logits, nullptr, nullptr, N_TGT2, F_OUT, 0);

    logsoftmax_kernel<<<N_TGT2, F_OUT>>>(p_logits, out_ls);
}

// round 9
// speedup vs baseline: 1.1405x; 1.1405x over previous
#include <cuda_runtime.h>
#include <cuda_bf16.h>
#include <math.h>
#include <stdint.h>

typedef __nv_bfloat16 bf16;

#define N_SRC1 200000
#define N_TGT1 50000
#define N_TGT2 10000
#define F_IN   256
#define F_HID  192
#define F_OUT  128
#define E1_MAX 1000000
#define E2_MAX 300000

// ---------------- scratch ----------------
__device__ bf16 g_m1_hi[N_TGT1 * F_IN];
__device__ bf16 g_m1_lo[N_TGT1 * F_IN];
__device__ float g_h1[(size_t)N_TGT1 * F_HID];
__device__ bf16 g_h1_hi[N_TGT2 * F_HID];
__device__ bf16 g_h1_lo[N_TGT2 * F_HID];
__device__ bf16 g_m2_hi[N_TGT2 * F_HID];
__device__ bf16 g_m2_lo[N_TGT2 * F_HID];
__device__ bf16 g_h2_hi[N_TGT2 * F_HID];
__device__ bf16 g_h2_lo[N_TGT2 * F_HID];
__device__ bf16 g_er_hi[N_TGT2 * F_HID];
__device__ bf16 g_er_lo[N_TGT2 * F_HID];
__device__ float g_logits[N_TGT2 * F_OUT];
// weight hi/lo planes
__device__ bf16 g_wl1_hi[F_HID * F_IN],  g_wl1_lo[F_HID * F_IN];
__device__ bf16 g_wr1_hi[F_HID * F_IN],  g_wr1_lo[F_HID * F_IN];
__device__ bf16 g_wl2_hi[F_HID * F_HID], g_wl2_lo[F_HID * F_HID];
__device__ bf16 g_wr2_hi[F_HID * F_HID], g_wr2_lo[F_HID * F_HID];
__device__ bf16 g_w1_hi[F_HID * F_HID],  g_w1_lo[F_HID * F_HID];
__device__ bf16 g_w2_hi[F_OUT * F_HID],  g_w2_lo[F_OUT * F_HID];
// CSR
__device__ int g_cnt1[N_TGT1];
__device__ int g_cnt2[N_TGT2];
__device__ int g_bsum1[1024];
__device__ int g_bsum2[1024];
__device__ int g_offs1[N_TGT1 + 1];
__device__ int g_offs2[N_TGT2 + 1];
__device__ int g_csr1[E1_MAX];
__device__ int g_csr2[E2_MAX];

#define SCAN_B 256

// ---------------- merged CSR build (both layers in one launch each) ----------------
__global__ void hist2_kernel(const int* __restrict__ tgt1, int E1, int* __restrict__ cnt1,
                             const int* __restrict__ tgt2, int E2, int* __restrict__ cnt2) {
    int i = blockIdx.x * blockDim.x + threadIdx.x;
    if (i < E1) atomicAdd(&cnt1[tgt1[i]], 1);
    else if (i < E1 + E2) atomicAdd(&cnt2[tgt2[i - E1]], 1);
}

__global__ void block_sum2_kernel(const int* __restrict__ cnt1, int n1, int* __restrict__ bsum1, int G1,
                                  const int* __restrict__ cnt2, int n2, int* __restrict__ bsum2) {
    __shared__ int sm[SCAN_B];
    int b = blockIdx.x;
    const int* cnt; int n; int* bsum; int bb;
    if (b < G1) { cnt = cnt1; n = n1; bsum = bsum1; bb = b; }
    else        { cnt = cnt2; n = n2; bsum = bsum2; bb = b - G1; }
    int t = threadIdx.x;
    int i = bb * SCAN_B + t;
    sm[t] = (i < n) ? cnt[i] : 0;
    __syncthreads();
    for (int off = SCAN_B / 2; off > 0; off >>= 1) {
        if (t < off) sm[t] += sm[t + off];
        __syncthreads();
    }
    if (t == 0) bsum[bb] = sm[0];
}

// grid=2; block 0 scans bsum1, block 1 scans bsum2 (shfl-based, 4 elems/thread)
__global__ void scan2_kernel(int* __restrict__ bsum1, int G1, int* __restrict__ total1,
                             int* __restrict__ bsum2, int G2, int* __restrict__ total2) {
    __shared__ int warp_sums[8];
    int* bsum = blockIdx.x ? bsum2 : bsum1;
    int G     = blockIdx.x ? G2 : G1;
    int* total = blockIdx.x ? total2 : total1;
    int t = threadIdx.x;
    int lane = t & 31, warp = t >> 5;
    int v[4];
    int base = t * 4;
#pragma unroll
    for (int q = 0; q < 4; q++) v[q] = (base + q < G) ? bsum[base + q] : 0;
    int mysum = v[0] + v[1] + v[2] + v[3];
    int run = mysum;
#pragma unroll
    for (int off = 1; off < 32; off <<= 1) {
        int u = __shfl_up_sync(0xffffffffu, run, off);
        if (lane >= off) run += u;
    }
    if (lane == 31) warp_sums[warp] = run;
    __syncthreads();
    int wpre = 0;
#pragma unroll
    for (int w = 0; w < 8; w++) {
        int ws = warp_sums[w];
        if (w < warp) wpre += ws;
    }
    int excl = wpre + run - mysum;
#pragma unroll
    for (int q = 0; q < 4; q++) {
        if (base + q < G) bsum[base + q] = excl;
        excl += v[q];
    }
    if (t == 255) *total = wpre + run;
}

__global__ void scatter2_kernel(const int* __restrict__ cnt1, int n1, const int* __restrict__ bsum1, int G1,
                                int* __restrict__ offs1, int* __restrict__ cursor1,
                                const int* __restrict__ cnt2, int n2, const int* __restrict__ bsum2,
                                int* __restrict__ offs2, int* __restrict__ cursor2) {
    __shared__ int sm[SCAN_B];
    int b = blockIdx.x;
    const int* cnt; int n; const int* bsum; int* offs; int* cursor; int bb;
    if (b < G1) { cnt = cnt1; n = n1; bsum = bsum1; offs = offs1; cursor = cursor1; bb = b; }
    else        { cnt = cnt2; n = n2; bsum = bsum2; offs = offs2; cursor = cursor2; bb = b - G1; }
    int t = threadIdx.x;
    int i = bb * SCAN_B + t;
    int v = (i < n) ? cnt[i] : 0;
    sm[t] = v;
    __syncthreads();
    for (int off = 1; off < SCAN_B; off <<= 1) {
        int u = (t >= off) ? sm[t - off] : 0;
        __syncthreads();
        sm[t] += u;
        __syncthreads();
    }
    if (i < n) {
        int o = bsum[bb] + sm[t] - v;
        offs[i] = o;
        cursor[i] = o;
    }
}

__global__ void fill2_kernel(const int* __restrict__ src1, const int* __restrict__ tgt1, int E1,
                             int* __restrict__ cursor1, int* __restrict__ csr1,
                             const int* __restrict__ src2, const int* __restrict__ tgt2, int E2,
                             int* __restrict__ cursor2, int* __restrict__ csr2) {
    int i = blockIdx.x * blockDim.x + threadIdx.x;
    if (i < E1) {
        int p = atomicAdd(&cursor1[tgt1[i]], 1);
        csr1[p] = src1[i];
    } else if (i < E1 + E2) {
        int j = i - E1;
        int p = atomicAdd(&cursor2[tgt2[j]], 1);
        csr2[p] = src2[j];
    }
}

// ---------------- splits ----------------
__device__ __forceinline__ void split2(float v, bf16& h, bf16& l) {
    bf16 hh = __float2bfloat16_rn(v);
    h = hh;
    l = __float2bfloat16_rn(v - __bfloat162float(hh));
}

__global__ void split_weights_kernel(const float* __restrict__ wl1, const float* __restrict__ wr1,
                                     const float* __restrict__ wl2, const float* __restrict__ wr2,
                                     const float* __restrict__ w1,  const float* __restrict__ w2) {
    int i = blockIdx.x * 256 + threadIdx.x;
    const int A = F_HID * F_IN;
    const int B = F_HID * F_HID;
    const int C = F_OUT * F_HID;
    float v; bf16 *hp, *lp; int o;
    if      (i < A)             { o = i;               v = wl1[o]; hp = g_wl1_hi; lp = g_wl1_lo; }
    else if (i < 2*A)           { o = i - A;           v = wr1[o]; hp = g_wr1_hi; lp = g_wr1_lo; }
    else if (i < 2*A + B)       { o = i - 2*A;         v = wl2[o]; hp = g_wl2_hi; lp = g_wl2_lo; }
    else if (i < 2*A + 2*B)     { o = i - 2*A - B;     v = wr2[o]; hp = g_wr2_hi; lp = g_wr2_lo; }
    else if (i < 2*A + 3*B)     { o = i - 2*A - 2*B;   v = w1[o];  hp = g_w1_hi;  lp = g_w1_lo; }
    else if (i < 2*A + 3*B + C) { o = i - 2*A - 3*B;   v = w2[o];  hp = g_w2_hi;  lp = g_w2_lo; }
    else return;
    bf16 h, l; split2(v, h, l);
    hp[o] = h; lp[o] = l;
}

// streaming 16-bit store (evict-first: don't pollute L2)
__device__ __forceinline__ void stcs_u16(bf16* p, bf16 v) {
    unsigned short s = *reinterpret_cast<unsigned short*>(&v);
    asm volatile("st.global.cs.u16 [%0], %1;" :: "l"(p), "h"(s) : "memory");
}

// ---------------- segment mean, feature-split half pass ----------------
// Processes FH columns starting at col0; working set = N_src * FH * 4 bytes (L2-resident).
// Row stride is F. Output written streaming (bypass L2).
template <int F, int FH>
__global__ void aggregate_half(const float* __restrict__ X, const int* __restrict__ csr,
                               const int* __restrict__ offs,
                               bf16* __restrict__ hi, bf16* __restrict__ lo, int col0) {
    int node = blockIdx.x;
    int t = threadIdx.x;   // 0..FH-1
    int s = offs[node], e = offs[node + 1];
    const float* Xc = X + col0 + t;
    float acc = 0.0f;
    int j = s;
    for (; j + 7 < e; j += 8) {
        int idx[8];
#pragma unroll
        for (int q = 0; q < 8; q++) idx[q] = __ldg(&csr[j + q]);
        float v[8];
#pragma unroll
        for (int q = 0; q < 8; q++) v[q] = Xc[(size_t)idx[q] * F];
        acc += ((v[0] + v[1]) + (v[2] + v[3])) + ((v[4] + v[5]) + (v[6] + v[7]));
    }
    for (; j < e; j++) acc += Xc[(size_t)__ldg(&csr[j]) * F];
    int deg = e - s;
    float m = acc * (1.0f / (float)(deg > 1 ? deg : 1));
    bf16 h, l; split2(m, h, l);
    size_t o = (size_t)node * F + col0 + t;
    stcs_u16(hi + o, h);
    stcs_u16(lo + o, l);
}

// ---------------- segment mean, single-pass (layer 2; source fits L2) ----------------
template <int F>
__global__ void aggregate_hilo(const float* __restrict__ X, const int* __restrict__ csr,
                               const int* __restrict__ offs,
                               bf16* __restrict__ hi, bf16* __restrict__ lo) {
    int node = blockIdx.x;
    int t = threadIdx.x;
    int s = offs[node], e = offs[node + 1];
    float acc = 0.0f;
    int j = s;
    for (; j + 7 < e; j += 8) {
        int idx[8];
#pragma unroll
        for (int q = 0; q < 8; q++) idx[q] = __ldg(&csr[j + q]);
        float v[8];
#pragma unroll
        for (int q = 0; q < 8; q++) v[q] = X[(size_t)idx[q] * F + t];
        acc += ((v[0] + v[1]) + (v[2] + v[3])) + ((v[4] + v[5]) + (v[6] + v[7]));
    }
    for (; j < e; j++) acc += X[(size_t)__ldg(&csr[j]) * F + t];
    int deg = e - s;
    float m = acc * (1.0f / (float)(deg > 1 ? deg : 1));
    bf16 h, l; split2(m, h, l);
    size_t o = (size_t)node * F + t;
    hi[o] = h; lo[o] = l;
}

// ---------------- bf16x3 tensor-core GEMM (register double-buffered) ----------------
#define BM 128
#define BN 64
#define BKT 32
#define SLDA 40

__device__ __forceinline__ void ldsm4(uint32_t r[4], uint32_t addr) {
    asm volatile("ldmatrix.sync.aligned.m8n8.x4.shared.b16 {%0,%1,%2,%3}, [%4];"
                 : "=r"(r[0]), "=r"(r[1]), "=r"(r[2]), "=r"(r[3]) : "r"(addr));
}
__device__ __forceinline__ void mma_bf16(float d[4], const uint32_t a[4], uint32_t b0, uint32_t b1) {
    asm volatile("mma.sync.aligned.m16n8k16.row.col.f32.bf16.bf16.f32 "
                 "{%0,%1,%2,%3},{%4,%5,%6,%7},{%8,%9},{%0,%1,%2,%3};"
                 : "+f"(d[0]), "+f"(d[1]), "+f"(d[2]), "+f"(d[3])
                 : "r"(a[0]), "r"(a[1]), "r"(a[2]), "r"(a[3]), "r"(b0), "r"(b1));
}

__device__ __forceinline__ void split8(const float f[8], uint4& h, uint4& l) {
    __nv_bfloat162 hh[4], ll[4];
#pragma unroll
    for (int i = 0; i < 4; i++) {
        bf16 h0, l0, h1, l1;
        split2(f[2 * i], h0, l0);
        split2(f[2 * i + 1], h1, l1);
        hh[i].x = h0; hh[i].y = h1;
        ll[i].x = l0; ll[i].y = l1;
    }
    h = *(uint4*)hh;
    l = *(uint4*)ll;
}

template <int K, bool F32SRC>
__device__ __forceinline__ void mma_phase(const void* __restrict__ Ahi_v, const bf16* __restrict__ Alo,
                                          const bf16* __restrict__ Whi, const bf16* __restrict__ Wlo,
                                          int M, int m0, int n0,
                                          bf16 (*sA)[SLDA], bf16 (*sW)[SLDA],
                                          float acc[2][4][4]) {
    int t = threadIdx.x;
    int lane = t & 31, warp = t >> 5;
    int wm = (warp & 3) * 32, wn = (warp >> 2) * 32;
    uint32_t sA_u = (uint32_t)__cvta_generic_to_shared(&sA[0][0]);
    uint32_t sW_u = (uint32_t)__cvta_generic_to_shared(&sW[0][0]);

    const int ar = t >> 1, ac = (t & 1) * 16;
    const int wr = t >> 2, wc = (t & 3) * 8;

    uint32_t a_off[2][2], b_off[2][2];
#pragma unroll
    for (int p = 0; p < 2; p++) {
#pragma unroll
        for (int mf = 0; mf < 2; mf++)
            a_off[p][mf] = sA_u + (uint32_t)(((p * BM + wm + mf * 16 + (lane & 15)) * SLDA + ((lane >> 4) * 8)) * 2);
#pragma unroll
        for (int np = 0; np < 2; np++)
            b_off[p][np] = sW_u + (uint32_t)(((p * BN + wn + np * 16 + (lane & 7) + ((lane >> 4) * 8)) * SLDA +
                                             (((lane >> 3) & 1) * 8)) * 2);
    }

    const bool av = (m0 + ar) < M;
    uint4 sh0, sh1, sl0, sl1, swh, swl;

    auto fetch = [&](int kt) {
        if (F32SRC) {
            const float* Xf = (const float*)Ahi_v;
            float f[16];
            if (av) {
                size_t abase = (size_t)(m0 + ar) * K + kt + ac;
#pragma unroll
                for (int q = 0; q < 4; q++)
                    *(float4*)&f[4 * q] = *(const float4*)(Xf + abase + 4 * q);
            } else {
#pragma unroll
                for (int q = 0; q < 16; q++) f[q] = 0.f;
            }
            split8(&f[0], sh0, sl0);
            split8(&f[8], sh1, sl1);
        } else {
            const bf16* Ahi = (const bf16*)Ahi_v;
            uint4 z = make_uint4(0, 0, 0, 0);
            size_t abase = (size_t)(m0 + ar) * K + kt + ac;
            sh0 = av ? *(const uint4*)(Ahi + abase)     : z;
            sh1 = av ? *(const uint4*)(Ahi + abase + 8) : z;
            sl0 = av ? *(const uint4*)(Alo + abase)     : z;
            sl1 = av ? *(const uint4*)(Alo + abase + 8) : z;
        }
        size_t wbase = (size_t)(n0 + wr) * K + kt + wc;
        swh = *(const uint4*)(Whi + wbase);
        swl = *(const uint4*)(Wlo + wbase);
    };

    fetch(0);
    for (int kt = 0; kt < K; kt += BKT) {
        __syncthreads();
        *(uint4*)&sA[ar][ac]          = sh0;
        *(uint4*)&sA[ar][ac + 8]      = sh1;
        *(uint4*)&sA[BM + ar][ac]     = sl0;
        *(uint4*)&sA[BM + ar][ac + 8] = sl1;
        *(uint4*)&sW[wr][wc]      = swh;
        *(uint4*)&sW[BN + wr][wc] = swl;
        __syncthreads();
        if (kt + BKT < K) fetch(kt + BKT);
#pragma unroll
        for (int ks = 0; ks < 2; ks++) {
            uint32_t a[2][2][4], b[2][2][4];
#pragma unroll
            for (int p = 0; p < 2; p++) {
#pragma unroll
                for (int mf = 0; mf < 2; mf++) ldsm4(a[p][mf], a_off[p][mf] + ks * 32);
#pragma unroll
                for (int np = 0; np < 2; np++) ldsm4(b[p][np], b_off[p][np] + ks * 32);
            }
#pragma unroll
            for (int mf = 0; mf < 2; mf++)
#pragma unroll
                for (int nf = 0; nf < 4; nf++) {
                    uint32_t bh0 = b[0][nf >> 1][(nf & 1) * 2], bh1 = b[0][nf >> 1][(nf & 1) * 2 + 1];
                    uint32_t bl0 = b[1][nf >> 1][(nf & 1) * 2], bl1 = b[1][nf >> 1][(nf & 1) * 2 + 1];
                    mma_bf16(acc[mf][nf], a[0][mf], bh0, bh1);
                    mma_bf16(acc[mf][nf], a[0][mf], bl0, bl1);
                    mma_bf16(acc[mf][nf], a[1][mf], bh0, bh1);
                }
        }
    }
}

template <int K1, int K2, bool A2F32, bool WF32, bool F32RELU, bool WHILO>
__global__ __launch_bounds__(256, 2) void gemm_mma(
    const bf16* __restrict__ A1hi, const bf16* __restrict__ A1lo,
    const void* __restrict__ A2hi, const bf16* __restrict__ A2lo,
    const bf16* __restrict__ W1hi, const bf16* __restrict__ W1lo,
    const bf16* __restrict__ W2hi, const bf16* __restrict__ W2lo,
    const float* __restrict__ bias,
    float* __restrict__ C, bf16* __restrict__ Ohi, bf16* __restrict__ Olo,
    int M, int N, int hilo_limit) {
    __shared__ bf16 sA[2 * BM][SLDA];
    __shared__ bf16 sW[2 * BN][SLDA];
    float acc[2][4][4];
#pragma unroll
    for (int i = 0; i < 2; i++)
#pragma unroll
        for (int j = 0; j < 4; j++)
#pragma unroll
            for (int k = 0; k < 4; k++) acc[i][j][k] = 0.f;

    int m0 = blockIdx.x * BM, n0 = blockIdx.y * BN;

    mma_phase<K1, false>(A1hi, A1lo, W1hi, W1lo, M, m0, n0, sA, sW, acc);
    if constexpr (K2 > 0)
        mma_phase<K2, A2F32>(A2hi, A2lo, W2hi, W2lo, M, m0, n0, sA, sW, acc);

    int t = threadIdx.x, lane = t & 31, warp = t >> 5;
    int wm = (warp & 3) * 32, wn = (warp >> 2) * 32;
#pragma unroll
    for (int mf = 0; mf < 2; mf++) {
        int row0 = m0 + wm + mf * 16 + (lane >> 2);
        int row1 = row0 + 8;
#pragma unroll
        for (int nf = 0; nf < 4; nf++) {
            int col = n0 + wn + nf * 8 + (lane & 3) * 2;
            float b0 = bias[col], b1 = bias[col + 1];
            float v00 = acc[mf][nf][0] + b0, v01 = acc[mf][nf][1] + b1;
            float v10 = acc[mf][nf][2] + b0, v11 = acc[mf][nf][3] + b1;
#pragma unroll
            for (int half = 0; half < 2; half++) {
                int row = half ? row1 : row0;
                float a0 = half ? v10 : v00;
                float a1 = half ? v11 : v01;
                if (row < M) {
                    if (WF32) {
                        float o0 = F32RELU ? fmaxf(a0, 0.f) : a0;
                        float o1 = F32RELU ? fmaxf(a1, 0.f) : a1;
                        *(float2*)&C[(size_t)row * N + col] = make_float2(o0, o1);
                    }
                    if (WHILO && row < hilo_limit) {
                        float r0 = fmaxf(a0, 0.f), r1 = fmaxf(a1, 0.f);
                        bf16 h0, l0, h1, l1;
                        split2(r0, h0, l0); split2(r1, h1, l1);
                        __nv_bfloat162 hv; hv.x = h0; hv.y = h1;
                        __nv_bfloat162 lv; lv.x = l0; lv.y = l1;
                        *(__nv_bfloat162*)&Ohi[(size_t)row * N + col] = hv;
                        *(__nv_bfloat162*)&Olo[(size_t)row * N + col] = lv;
                    }
                }
            }
        }
    }
}

// ---------------- log_softmax ----------------
__global__ void logsoftmax_kernel(const float* __restrict__ logits, float* __restrict__ out) {
    __shared__ float red[128];
    int row = blockIdx.x;
    int t = threadIdx.x;
    float v = logits[row * F_OUT + t];
    red[t] = v;
    __syncthreads();
    for (int off = 64; off > 0; off >>= 1) {
        if (t < off) red[t] = fmaxf(red[t], red[t + off]);
        __syncthreads();
    }
    float mx = red[0];
    __syncthreads();
    red[t] = expf(v - mx);
    __syncthreads();
    for (int off = 64; off > 0; off >>= 1) {
        if (t < off) red[t] += red[t + off];
        __syncthreads();
    }
    float lse = logf(red[0]);
    out[row * F_OUT + t] = v - mx - lse;
}

// ---------------- launch (single stream, graph-capture safe) ----------------
extern "C" void kernel_launch(void* const* d_in, const int* in_sizes, int n_in,
                              void* d_out, int out_size) {
    const float* x   = (const float*)d_in[0];
    const int*   ei1 = (const int*)d_in[1];
    const int*   ei2 = (const int*)d_in[2];
    const float* Wl1 = (const float*)d_in[3];
    const float* bl1 = (const float*)d_in[4];
    const float* Wr1 = (const float*)d_in[5];
    const float* Wl2 = (const float*)d_in[6];
    const float* bl2 = (const float*)d_in[7];
    const float* Wr2 = (const float*)d_in[8];
    const float* W1  = (const float*)d_in[9];
    const float* b1  = (const float*)d_in[10];
    const float* W2  = (const float*)d_in[11];
    const float* b2  = (const float*)d_in[12];

    int E1 = in_sizes[1] / 2;
    int E2 = in_sizes[2] / 2;
    const int* src1 = ei1;
    const int* tgt1 = ei1 + E1;
    const int* src2 = ei2;
    const int* tgt2 = ei2 + E2;

    float* out_ls  = (float*)d_out;
    float* out_emb = (float*)d_out + N_TGT2 * F_OUT;

    bf16 *p_m1hi, *p_m1lo, *p_h1hi, *p_h1lo, *p_m2hi, *p_m2lo;
    bf16 *p_h2hi, *p_h2lo, *p_erhi, *p_erlo;
    bf16 *p_wl1h, *p_wl1l, *p_wr1h, *p_wr1l, *p_wl2h, *p_wl2l, *p_wr2h, *p_wr2l;
    bf16 *p_w1h, *p_w1l, *p_w2h, *p_w2l;
    float *p_h1, *p_logits;
    int *p_cnt1, *p_cnt2, *p_bsum1, *p_bsum2, *p_offs1, *p_offs2, *p_csr1, *p_csr2;
    cudaGetSymbolAddress((void**)&p_m1hi, g_m1_hi); cudaGetSymbolAddress((void**)&p_m1lo, g_m1_lo);
    cudaGetSymbolAddress((void**)&p_h1hi, g_h1_hi); cudaGetSymbolAddress((void**)&p_h1lo, g_h1_lo);
    cudaGetSymbolAddress((void**)&p_m2hi, g_m2_hi); cudaGetSymbolAddress((void**)&p_m2lo, g_m2_lo);
    cudaGetSymbolAddress((void**)&p_h2hi, g_h2_hi); cudaGetSymbolAddress((void**)&p_h2lo, g_h2_lo);
    cudaGetSymbolAddress((void**)&p_erhi, g_er_hi); cudaGetSymbolAddress((void**)&p_erlo, g_er_lo);
    cudaGetSymbolAddress((void**)&p_wl1h, g_wl1_hi); cudaGetSymbolAddress((void**)&p_wl1l, g_wl1_lo);
    cudaGetSymbolAddress((void**)&p_wr1h, g_wr1_hi); cudaGetSymbolAddress((void**)&p_wr1l, g_wr1_lo);
    cudaGetSymbolAddress((void**)&p_wl2h, g_wl2_hi); cudaGetSymbolAddress((void**)&p_wl2l, g_wl2_lo);
    cudaGetSymbolAddress((void**)&p_wr2h, g_wr2_hi); cudaGetSymbolAddress((void**)&p_wr2l, g_wr2_lo);
    cudaGetSymbolAddress((void**)&p_w1h,  g_w1_hi);  cudaGetSymbolAddress((void**)&p_w1l,  g_w1_lo);
    cudaGetSymbolAddress((void**)&p_w2h,  g_w2_hi);  cudaGetSymbolAddress((void**)&p_w2l,  g_w2_lo);
    cudaGetSymbolAddress((void**)&p_h1,     g_h1);
    cudaGetSymbolAddress((void**)&p_logits, g_logits);
    cudaGetSymbolAddress((void**)&p_cnt1,  g_cnt1);
    cudaGetSymbolAddress((void**)&p_cnt2,  g_cnt2);
    cudaGetSymbolAddress((void**)&p_bsum1, g_bsum1);
    cudaGetSymbolAddress((void**)&p_bsum2, g_bsum2);
    cudaGetSymbolAddress((void**)&p_offs1, g_offs1);
    cudaGetSymbolAddress((void**)&p_offs2, g_offs2);
    cudaGetSymbolAddress((void**)&p_csr1,  g_csr1);
    cudaGetSymbolAddress((void**)&p_csr2,  g_csr2);

    const int G1 = (N_TGT1 + SCAN_B - 1) / SCAN_B;
    const int G2 = (N_TGT2 + SCAN_B - 1) / SCAN_B;

    // weight splits
    {
        const int total = 2 * (F_HID * F_IN) + 3 * (F_HID * F_HID) + F_OUT * F_HID;
        split_weights_kernel<<<(total + 255) / 256, 256>>>(Wl1, Wr1, Wl2, Wr2, W1, W2);
    }

    // ---- both layers' CSR builds, merged ----
    cudaMemsetAsync(p_cnt1, 0, N_TGT1 * sizeof(int));
    cudaMemsetAsync(p_cnt2, 0, N_TGT2 * sizeof(int));
    hist2_kernel<<<(E1 + E2 + 255) / 256, 256>>>(tgt1, E1, p_cnt1, tgt2, E2, p_cnt2);
    block_sum2_kernel<<<G1 + G2, SCAN_B>>>(p_cnt1, N_TGT1, p_bsum1, G1, p_cnt2, N_TGT2, p_bsum2);
    scan2_kernel<<<2, 256>>>(p_bsum1, G1, p_offs1 + N_TGT1, p_bsum2, G2, p_offs2 + N_TGT2);
    scatter2_kernel<<<G1 + G2, SCAN_B>>>(p_cnt1, N_TGT1, p_bsum1, G1, p_offs1, p_cnt1,
                                         p_cnt2, N_TGT2, p_bsum2, p_offs2, p_cnt2);
    fill2_kernel<<<(E1 + E2 + 255) / 256, 256>>>(src1, tgt1, E1, p_cnt1, p_csr1,
                                                 src2, tgt2, E2, p_cnt2, p_csr2);

    // ---- layer-1 aggregate: two half-feature passes (each L2-resident) ----
    aggregate_half<F_IN, 128><<<N_TGT1, 128>>>(x, p_csr1, p_offs1, p_m1hi, p_m1lo, 0);
    aggregate_half<F_IN, 128><<<N_TGT1, 128>>>(x, p_csr1, p_offs1, p_m1hi, p_m1lo, 128);

    // h1 = relu(mean1 @ Wl1^T + x[:50k] @ Wr1^T + bl1)
    gemm_mma<F_IN, F_IN, true, true, true, true>
        <<<dim3((N_TGT1 + BM - 1) / BM, F_HID / BN), 256>>>(
            p_m1hi, p_m1lo, x, nullptr, p_wl1h, p_wl1l, p_wr1h, p_wr1l,
            bl1, p_h1, p_h1hi, p_h1lo, N_TGT1, F_HID, N_TGT2);

    // ---- layer-2 aggregate (h1 fits L2, single pass) ----
    aggregate_hilo<F_HID><<<N_TGT2, F_HID>>>(p_h1, p_csr2, p_offs2, p_m2hi, p_m2lo);

    // h2 = relu(mean2 @ Wl2^T + h1[:10k] @ Wr2^T + bl2)
    gemm_mma<F_HID, F_HID, false, false, false, true>
        <<<dim3((N_TGT2 + BM - 1) / BM, F_HID / BN), 256>>>(
            p_m2hi, p_m2lo, p_h1hi, p_h1lo, p_wl2h, p_wl2l, p_wr2h, p_wr2l,
            bl2, nullptr, p_h2hi, p_h2lo, N_TGT2, F_HID, N_TGT2);

    // embedding = h2 @ W1^T + b1
    gemm_mma<F_HID, 0, false, true, false, true>
        <<<dim3((N_TGT2 + BM - 1) / BM, F_HID / BN), 256>>>(
            p_h2hi, p_h2lo, nullptr, nullptr, p_w1h, p_w1l, nullptr, nullptr,
            b1, out_emb, p_erhi, p_erlo, N_TGT2, F_HID, N_TGT2);

    // logits = relu(emb) @ W2^T + b2
    gemm_mma<F_HID, 0, false, true, false, false>
        <<<dim3((N_TGT2 + BM - 1) / BM, F_OUT / BN), 256>>>(
            p_erhi, p_erlo, nullptr, nullptr, p_w2h, p_w2l, nullptr, nullptr,
            b2, p_logits, nullptr, nullptr, N_TGT2, F_OUT, 0);

    logsoftmax_kernel<<<N_TGT2, F_OUT>>>(p_logits, out_ls);
}

// round 13
// speedup vs baseline: 1.1509x; 1.0092x over previous
#include <cuda_runtime.h>
#include <cuda_bf16.h>
#include <math.h>
#include <stdint.h>

typedef __nv_bfloat16 bf16;

#define N_SRC1 200000
#define N_TGT1 50000
#define N_TGT2 10000
#define F_IN   256
#define F_HID  192
#define F_OUT  128
#define E1_MAX 1000000
#define E2_MAX 300000

// ---------------- scratch ----------------
__device__ bf16 g_m1_hi[N_TGT1 * F_IN];
__device__ bf16 g_m1_lo[N_TGT1 * F_IN];
__device__ float g_h1[(size_t)N_TGT1 * F_HID];
__device__ bf16 g_h1_hi[N_TGT2 * F_HID];
__device__ bf16 g_h1_lo[N_TGT2 * F_HID];
__device__ bf16 g_m2_hi[N_TGT2 * F_HID];
__device__ bf16 g_m2_lo[N_TGT2 * F_HID];
__device__ bf16 g_h2_hi[N_TGT2 * F_HID];
__device__ bf16 g_h2_lo[N_TGT2 * F_HID];
__device__ bf16 g_er_hi[N_TGT2 * F_HID];
__device__ bf16 g_er_lo[N_TGT2 * F_HID];
__device__ float g_logits[N_TGT2 * F_OUT];
// weight hi/lo planes
__device__ bf16 g_wl1_hi[F_HID * F_IN],  g_wl1_lo[F_HID * F_IN];
__device__ bf16 g_wr1_hi[F_HID * F_IN],  g_wr1_lo[F_HID * F_IN];
__device__ bf16 g_wl2_hi[F_HID * F_HID], g_wl2_lo[F_HID * F_HID];
__device__ bf16 g_wr2_hi[F_HID * F_HID], g_wr2_lo[F_HID * F_HID];
__device__ bf16 g_w1_hi[F_HID * F_HID],  g_w1_lo[F_HID * F_HID];
__device__ bf16 g_w2_hi[F_OUT * F_HID],  g_w2_lo[F_OUT * F_HID];
// CSR
__device__ int g_cnt1[N_TGT1];
__device__ int g_cnt2[N_TGT2];
__device__ int g_bsum1[1024];
__device__ int g_bsum2[1024];
__device__ int g_offs1[N_TGT1 + 1];
__device__ int g_offs2[N_TGT2 + 1];
__device__ int g_csr1[E1_MAX];
__device__ int g_csr2[E2_MAX];

#define SCAN_B 256

// ---------------- merged CSR build ----------------
__global__ void hist2_kernel(const int* __restrict__ tgt1, int E1, int* __restrict__ cnt1,
                             const int* __restrict__ tgt2, int E2, int* __restrict__ cnt2) {
    int i = blockIdx.x * blockDim.x + threadIdx.x;
    if (i < E1) atomicAdd(&cnt1[tgt1[i]], 1);
    else if (i < E1 + E2) atomicAdd(&cnt2[tgt2[i - E1]], 1);
}

__global__ void block_sum2_kernel(const int* __restrict__ cnt1, int n1, int* __restrict__ bsum1, int G1,
                                  const int* __restrict__ cnt2, int n2, int* __restrict__ bsum2) {
    __shared__ int sm[SCAN_B];
    int b = blockIdx.x;
    const int* cnt; int n; int* bsum; int bb;
    if (b < G1) { cnt = cnt1; n = n1; bsum = bsum1; bb = b; }
    else        { cnt = cnt2; n = n2; bsum = bsum2; bb = b - G1; }
    int t = threadIdx.x;
    int i = bb * SCAN_B + t;
    sm[t] = (i < n) ? cnt[i] : 0;
    __syncthreads();
    for (int off = SCAN_B / 2; off > 0; off >>= 1) {
        if (t < off) sm[t] += sm[t + off];
        __syncthreads();
    }
    if (t == 0) bsum[bb] = sm[0];
}

__global__ void scan2_kernel(int* __restrict__ bsum1, int G1, int* __restrict__ total1,
                             int* __restrict__ bsum2, int G2, int* __restrict__ total2) {
    __shared__ int warp_sums[8];
    int* bsum = blockIdx.x ? bsum2 : bsum1;
    int G     = blockIdx.x ? G2 : G1;
    int* total = blockIdx.x ? total2 : total1;
    int t = threadIdx.x;
    int lane = t & 31, warp = t >> 5;
    int v[4];
    int base = t * 4;
#pragma unroll
    for (int q = 0; q < 4; q++) v[q] = (base + q < G) ? bsum[base + q] : 0;
    int mysum = v[0] + v[1] + v[2] + v[3];
    int run = mysum;
#pragma unroll
    for (int off = 1; off < 32; off <<= 1) {
        int u = __shfl_up_sync(0xffffffffu, run, off);
        if (lane >= off) run += u;
    }
    if (lane == 31) warp_sums[warp] = run;
    __syncthreads();
    int wpre = 0;
#pragma unroll
    for (int w = 0; w < 8; w++) {
        int ws = warp_sums[w];
        if (w < warp) wpre += ws;
    }
    int excl = wpre + run - mysum;
#pragma unroll
    for (int q = 0; q < 4; q++) {
        if (base + q < G) bsum[base + q] = excl;
        excl += v[q];
    }
    if (t == 255) *total = wpre + run;
}

__global__ void scatter2_kernel(const int* __restrict__ cnt1, int n1, const int* __restrict__ bsum1, int G1,
                                int* __restrict__ offs1, int* __restrict__ cursor1,
                                const int* __restrict__ cnt2, int n2, const int* __restrict__ bsum2,
                                int* __restrict__ offs2, int* __restrict__ cursor2) {
    __shared__ int sm[SCAN_B];
    int b = blockIdx.x;
    const int* cnt; int n; const int* bsum; int* offs; int* cursor; int bb;
    if (b < G1) { cnt = cnt1; n = n1; bsum = bsum1; offs = offs1; cursor = cursor1; bb = b; }
    else        { cnt = cnt2; n = n2; bsum = bsum2; offs = offs2; cursor = cursor2; bb = b - G1; }
    int t = threadIdx.x;
    int i = bb * SCAN_B + t;
    int v = (i < n) ? cnt[i] : 0;
    sm[t] = v;
    __syncthreads();
    for (int off = 1; off < SCAN_B; off <<= 1) {
        int u = (t >= off) ? sm[t - off] : 0;
        __syncthreads();
        sm[t] += u;
        __syncthreads();
    }
    if (i < n) {
        int o = bsum[bb] + sm[t] - v;
        offs[i] = o;
        cursor[i] = o;
    }
}

__global__ void fill2_kernel(const int* __restrict__ src1, const int* __restrict__ tgt1, int E1,
                             int* __restrict__ cursor1, int* __restrict__ csr1,
                             const int* __restrict__ src2, const int* __restrict__ tgt2, int E2,
                             int* __restrict__ cursor2, int* __restrict__ csr2) {
    int i = blockIdx.x * blockDim.x + threadIdx.x;
    if (i < E1) {
        int p = atomicAdd(&cursor1[tgt1[i]], 1);
        csr1[p] = src1[i];
    } else if (i < E1 + E2) {
        int j = i - E1;
        int p = atomicAdd(&cursor2[tgt2[j]], 1);
        csr2[p] = src2[j];
    }
}

// ---------------- splits ----------------
__device__ __forceinline__ void split2(float v, bf16& h, bf16& l) {
    bf16 hh = __float2bfloat16_rn(v);
    h = hh;
    l = __float2bfloat16_rn(v - __bfloat162float(hh));
}

__global__ void split_weights_kernel(const float* __restrict__ wl1, const float* __restrict__ wr1,
                                     const float* __restrict__ wl2, const float* __restrict__ wr2,
                                     const float* __restrict__ w1,  const float* __restrict__ w2) {
    int i = blockIdx.x * 256 + threadIdx.x;
    const int A = F_HID * F_IN;
    const int B = F_HID * F_HID;
    const int C = F_OUT * F_HID;
    float v; bf16 *hp, *lp; int o;
    if      (i < A)             { o = i;               v = wl1[o]; hp = g_wl1_hi; lp = g_wl1_lo; }
    else if (i < 2*A)           { o = i - A;           v = wr1[o]; hp = g_wr1_hi; lp = g_wr1_lo; }
    else if (i < 2*A + B)       { o = i - 2*A;         v = wl2[o]; hp = g_wl2_hi; lp = g_wl2_lo; }
    else if (i < 2*A + 2*B)     { o = i - 2*A - B;     v = wr2[o]; hp = g_wr2_hi; lp = g_wr2_lo; }
    else if (i < 2*A + 3*B)     { o = i - 2*A - 2*B;   v = w1[o];  hp = g_w1_hi;  lp = g_w1_lo; }
    else if (i < 2*A + 3*B + C) { o = i - 2*A - 3*B;   v = w2[o];  hp = g_w2_hi;  lp = g_w2_lo; }
    else return;
    bf16 h, l; split2(v, h, l);
    hp[o] = h; lp[o] = l;
}

// streaming 16-bit store
__device__ __forceinline__ void stcs_u16(bf16* p, bf16 v) {
    unsigned short s = *reinterpret_cast<unsigned short*>(&v);
    asm volatile("st.global.cs.u16 [%0], %1;" :: "l"(p), "h"(s) : "memory");
}

// ---------------- segment mean, feature-split half pass ----------------
template <int F, int FH>
__global__ void aggregate_half(const float* __restrict__ X, const int* __restrict__ csr,
                               const int* __restrict__ offs,
                               bf16* __restrict__ hi, bf16* __restrict__ lo, int col0) {
    int node = blockIdx.x;
    int t = threadIdx.x;
    int s = offs[node], e = offs[node + 1];
    const float* Xc = X + col0 + t;
    float acc = 0.0f;
    int j = s;
    for (; j + 7 < e; j += 8) {
        int idx[8];
#pragma unroll
        for (int q = 0; q < 8; q++) idx[q] = __ldg(&csr[j + q]);
        float v[8];
#pragma unroll
        for (int q = 0; q < 8; q++) v[q] = Xc[(size_t)idx[q] * F];
        acc += ((v[0] + v[1]) + (v[2] + v[3])) + ((v[4] + v[5]) + (v[6] + v[7]));
    }
    for (; j < e; j++) acc += Xc[(size_t)__ldg(&csr[j]) * F];
    int deg = e - s;
    float m = acc * (1.0f / (float)(deg > 1 ? deg : 1));
    bf16 h, l; split2(m, h, l);
    size_t o = (size_t)node * F + col0 + t;
    stcs_u16(hi + o, h);
    stcs_u16(lo + o, l);
}

// ---------------- segment mean, single-pass (layer 2) ----------------
template <int F>
__global__ void aggregate_hilo(const float* __restrict__ X, const int* __restrict__ csr,
                               const int* __restrict__ offs,
                               bf16* __restrict__ hi, bf16* __restrict__ lo) {
    int node = blockIdx.x;
    int t = threadIdx.x;
    int s = offs[node], e = offs[node + 1];
    float acc = 0.0f;
    int j = s;
    for (; j + 7 < e; j += 8) {
        int idx[8];
#pragma unroll
        for (int q = 0; q < 8; q++) idx[q] = __ldg(&csr[j + q]);
        float v[8];
#pragma unroll
        for (int q = 0; q < 8; q++) v[q] = X[(size_t)idx[q] * F + t];
        acc += ((v[0] + v[1]) + (v[2] + v[3])) + ((v[4] + v[5]) + (v[6] + v[7]));
    }
    for (; j < e; j++) acc += X[(size_t)__ldg(&csr[j]) * F + t];
    int deg = e - s;
    float m = acc * (1.0f / (float)(deg > 1 ? deg : 1));
    bf16 h, l; split2(m, h, l);
    size_t o = (size_t)node * F + t;
    hi[o] = h; lo[o] = l;
}

// ---------------- shared MMA primitives ----------------
#define SLDA 40

__device__ __forceinline__ void ldsm4(uint32_t r[4], uint32_t addr) {
    asm volatile("ldmatrix.sync.aligned.m8n8.x4.shared.b16 {%0,%1,%2,%3}, [%4];"
                 : "=r"(r[0]), "=r"(r[1]), "=r"(r[2]), "=r"(r[3]) : "r"(addr));
}
__device__ __forceinline__ void mma_bf16(float d[4], const uint32_t a[4], uint32_t b0, uint32_t b1) {
    asm volatile("mma.sync.aligned.m16n8k16.row.col.f32.bf16.bf16.f32 "
                 "{%0,%1,%2,%3},{%4,%5,%6,%7},{%8,%9},{%0,%1,%2,%3};"
                 : "+f"(d[0]), "+f"(d[1]), "+f"(d[2]), "+f"(d[3])
                 : "r"(a[0]), "r"(a[1]), "r"(a[2]), "r"(a[3]), "r"(b0), "r"(b1));
}

__device__ __forceinline__ void split8(const float f[8], uint4& h, uint4& l) {
    __nv_bfloat162 hh[4], ll[4];
#pragma unroll
    for (int i = 0; i < 4; i++) {
        bf16 h0, l0, h1, l1;
        split2(f[2 * i], h0, l0);
        split2(f[2 * i + 1], h1, l1);
        hh[i].x = h0; hh[i].y = h1;
        ll[i].x = l0; ll[i].y = l1;
    }
    h = *(uint4*)hh;
    l = *(uint4*)ll;
}

// ================= gemm1: BM=128 x BN=192 (full N), bf16x3, mma.sync =================
// 256 threads = 8 warps, warp grid 2(m) x 4(n), warp tile 64x48.
// Tiles live in DYNAMIC shared memory (51200 B > 48KB static limit).
#define G1BM 128
#define G1BN 192
#define G1BK 32
#define G1_SA_ELEMS (2 * G1BM * SLDA)                    // 10240 bf16 = 20480 B
#define G1_SMEM_BYTES ((2 * G1BM + 2 * G1BN) * SLDA * 2) // 51200 B

template <int K, bool F32SRC>
__device__ __forceinline__ void mma_phase192(const void* __restrict__ Ahi_v, const bf16* __restrict__ Alo,
                                             const bf16* __restrict__ Whi, const bf16* __restrict__ Wlo,
                                             int M, int m0,
                                             bf16* sA, bf16* sW,
                                             float acc[4][6][4]) {
    int t = threadIdx.x;
    int lane = t & 31, warp = t >> 5;
    int wm = (warp & 1) * 64;        // 2 m-tiles of 64
    int wn = (warp >> 1) * 48;       // 4 n-tiles of 48
    uint32_t sA_u = (uint32_t)__cvta_generic_to_shared(sA);
    uint32_t sW_u = (uint32_t)__cvta_generic_to_shared(sW);

    const int ar = t >> 1, ac = (t & 1) * 16;   // A loader: 128 rows x 32 cols
    const int wrr = t >> 2, wc = (t & 3) * 8;   // W loader: rows wrr, wrr+64, wrr+128

    uint32_t a_off[2][4], b_off[2][3];
#pragma unroll
    for (int p = 0; p < 2; p++) {
#pragma unroll
        for (int mf = 0; mf < 4; mf++)
            a_off[p][mf] = sA_u + (uint32_t)(((p * G1BM + wm + mf * 16 + (lane & 15)) * SLDA + ((lane >> 4) * 8)) * 2);
#pragma unroll
        for (int nb = 0; nb < 3; nb++)
            b_off[p][nb] = sW_u + (uint32_t)(((p * G1BN + wn + nb * 16 + (lane & 7) + ((lane >> 4) * 8)) * SLDA +
                                             (((lane >> 3) & 1) * 8)) * 2);
    }

    const bool av = (m0 + ar) < M;
    uint4 sh0, sh1, sl0, sl1;   // staged A tile only

    auto fetchA = [&](int kt) {
        if (F32SRC) {
            const float* Xf = (const float*)Ahi_v;
            float f[16];
            if (av) {
                size_t abase = (size_t)(m0 + ar) * K + kt + ac;
#pragma unroll
                for (int q = 0; q < 4; q++)
                    *(float4*)&f[4 * q] = *(const float4*)(Xf + abase + 4 * q);
            } else {
#pragma unroll
                for (int q = 0; q < 16; q++) f[q] = 0.f;
            }
            split8(&f[0], sh0, sl0);
            split8(&f[8], sh1, sl1);
        } else {
            const bf16* Ahi = (const bf16*)Ahi_v;
            uint4 z = make_uint4(0, 0, 0, 0);
            size_t abase = (size_t)(m0 + ar) * K + kt + ac;
            sh0 = av ? *(const uint4*)(Ahi + abase)     : z;
            sh1 = av ? *(const uint4*)(Ahi + abase + 8) : z;
            sl0 = av ? *(const uint4*)(Alo + abase)     : z;
            sl1 = av ? *(const uint4*)(Alo + abase + 8) : z;
        }
    };

    fetchA(0);
    for (int kt = 0; kt < K; kt += G1BK) {
        __syncthreads();
        *(uint4*)&sA[ar * SLDA + ac]                  = sh0;
        *(uint4*)&sA[ar * SLDA + ac + 8]              = sh1;
        *(uint4*)&sA[(G1BM + ar) * SLDA + ac]         = sl0;
        *(uint4*)&sA[(G1BM + ar) * SLDA + ac + 8]     = sl1;
        // W: 192 rows x 32 cols, hi+lo (direct loads; weights are L2-hot)
#pragma unroll
        for (int rr = 0; rr < 3; rr++) {
            int r = wrr + rr * 64;
            size_t wbase = (size_t)r * K + kt + wc;
            *(uint4*)&sW[r * SLDA + wc]            = *(const uint4*)(Whi + wbase);
            *(uint4*)&sW[(G1BN + r) * SLDA + wc]   = *(const uint4*)(Wlo + wbase);
        }
        __syncthreads();
        if (kt + G1BK < K) fetchA(kt + G1BK);
#pragma unroll
        for (int ks = 0; ks < 2; ks++) {
            uint32_t a[2][4][4], b[2][3][4];
#pragma unroll
            for (int p = 0; p < 2; p++) {
#pragma unroll
                for (int mf = 0; mf < 4; mf++) ldsm4(a[p][mf], a_off[p][mf] + ks * 32);
#pragma unroll
                for (int nb = 0; nb < 3; nb++) ldsm4(b[p][nb], b_off[p][nb] + ks * 32);
            }
#pragma unroll
            for (int mf = 0; mf < 4; mf++)
#pragma unroll
                for (int nf = 0; nf < 6; nf++) {
                    uint32_t bh0 = b[0][nf >> 1][(nf & 1) * 2], bh1 = b[0][nf >> 1][(nf & 1) * 2 + 1];
                    uint32_t bl0 = b[1][nf >> 1][(nf & 1) * 2], bl1 = b[1][nf >> 1][(nf & 1) * 2 + 1];
                    mma_bf16(acc[mf][nf], a[0][mf], bh0, bh1);  // hi*hi
                    mma_bf16(acc[mf][nf], a[0][mf], bl0, bl1);  // hi*lo
                    mma_bf16(acc[mf][nf], a[1][mf], bh0, bh1);  // lo*hi
                }
        }
    }
}

__global__ __launch_bounds__(256, 1) void gemm1_n192(
    const bf16* __restrict__ A1hi, const bf16* __restrict__ A1lo,
    const float* __restrict__ x,
    const bf16* __restrict__ W1hi, const bf16* __restrict__ W1lo,
    const bf16* __restrict__ W2hi, const bf16* __restrict__ W2lo,
    const float* __restrict__ bias,
    float* __restrict__ C, bf16* __restrict__ Ohi, bf16* __restrict__ Olo,
    int M, int hilo_limit) {
    extern __shared__ bf16 g1_smem[];
    bf16* sA = g1_smem;                 // [2*G1BM][SLDA]
    bf16* sW = g1_smem + G1_SA_ELEMS;   // [2*G1BN][SLDA]
    float acc[4][6][4];
#pragma unroll
    for (int i = 0; i < 4; i++)
#pragma unroll
        for (int j = 0; j < 6; j++)
#pragma unroll
            for (int k = 0; k < 4; k++) acc[i][j][k] = 0.f;

    int m0 = blockIdx.x * G1BM;

    mma_phase192<F_IN, false>(A1hi, A1lo, W1hi, W1lo, M, m0, sA, sW, acc);
    mma_phase192<F_IN, true >(x,    nullptr, W2hi, W2lo, M, m0, sA, sW, acc);

    int t = threadIdx.x, lane = t & 31, warp = t >> 5;
    int wm = (warp & 1) * 64, wn = (warp >> 1) * 48;
#pragma unroll
    for (int mf = 0; mf < 4; mf++) {
        int row0 = m0 + wm + mf * 16 + (lane >> 2);
        int row1 = row0 + 8;
#pragma unroll
        for (int nf = 0; nf < 6; nf++) {
            int col = wn + nf * 8 + (lane & 3) * 2;
            float b0 = bias[col], b1 = bias[col + 1];
            float v00 = acc[mf][nf][0] + b0, v01 = acc[mf][nf][1] + b1;
            float v10 = acc[mf][nf][2] + b0, v11 = acc[mf][nf][3] + b1;
#pragma unroll
            for (int half = 0; half < 2; half++) {
                int row = half ? row1 : row0;
                float a0 = half ? v10 : v00;
                float a1 = half ? v11 : v01;
                if (row < M) {
                    float o0 = fmaxf(a0, 0.f);
                    float o1 = fmaxf(a1, 0.f);
                    *(float2*)&C[(size_t)row * F_HID + col] = make_float2(o0, o1);
                    if (row < hilo_limit) {
                        bf16 h0, l0, h1, l1;
                        split2(o0, h0, l0); split2(o1, h1, l1);
                        __nv_bfloat162 hv; hv.x = h0; hv.y = h1;
                        __nv_bfloat162 lv; lv.x = l0; lv.y = l1;
                        *(__nv_bfloat162*)&Ohi[(size_t)row * F_HID + col] = hv;
                        *(__nv_bfloat162*)&Olo[(size_t)row * F_HID + col] = lv;
                    }
                }
            }
        }
    }
}

// ---------------- bf16x3 mma.sync GEMM (small GEMMs 2-4; round-9 proven) ----------------
#define BM 128
#define BN 64
#define BKT 32

template <int K>
__device__ __forceinline__ void mma_phase(const bf16* __restrict__ Ahi, const bf16* __restrict__ Alo,
                                          const bf16* __restrict__ Whi, const bf16* __restrict__ Wlo,
                                          int M, int m0, int n0,
                                          bf16 (*sA)[SLDA], bf16 (*sW)[SLDA],
                                          float acc[2][4][4]) {
    int t = threadIdx.x;
    int lane = t & 31, warp = t >> 5;
    int wm = (warp & 3) * 32, wn = (warp >> 2) * 32;
    uint32_t sA_u = (uint32_t)__cvta_generic_to_shared(&sA[0][0]);
    uint32_t sW_u = (uint32_t)__cvta_generic_to_shared(&sW[0][0]);

    const int ar = t >> 1, ac = (t & 1) * 16;
    const int wr = t >> 2, wc = (t & 3) * 8;

    uint32_t a_off[2][2], b_off[2][2];
#pragma unroll
    for (int p = 0; p < 2; p++) {
#pragma unroll
        for (int mf = 0; mf < 2; mf++)
            a_off[p][mf] = sA_u + (uint32_t)(((p * BM + wm + mf * 16 + (lane & 15)) * SLDA + ((lane >> 4) * 8)) * 2);
#pragma unroll
        for (int np = 0; np < 2; np++)
            b_off[p][np] = sW_u + (uint32_t)(((p * BN + wn + np * 16 + (lane & 7) + ((lane >> 4) * 8)) * SLDA +
                                             (((lane >> 3) & 1) * 8)) * 2);
    }

    const bool av = (m0 + ar) < M;
    uint4 sh0, sh1, sl0, sl1, swh, swl;

    auto fetch = [&](int kt) {
        uint4 z = make_uint4(0, 0, 0, 0);
        size_t abase = (size_t)(m0 + ar) * K + kt + ac;
        sh0 = av ? *(const uint4*)(Ahi + abase)     : z;
        sh1 = av ? *(const uint4*)(Ahi + abase + 8) : z;
        sl0 = av ? *(const uint4*)(Alo + abase)     : z;
        sl1 = av ? *(const uint4*)(Alo + abase + 8) : z;
        size_t wbase = (size_t)(n0 + wr) * K + kt + wc;
        swh = *(const uint4*)(Whi + wbase);
        swl = *(const uint4*)(Wlo + wbase);
    };

    fetch(0);
    for (int kt = 0; kt < K; kt += BKT) {
        __syncthreads();
        *(uint4*)&sA[ar][ac]          = sh0;
        *(uint4*)&sA[ar][ac + 8]      = sh1;
        *(uint4*)&sA[BM + ar][ac]     = sl0;
        *(uint4*)&sA[BM + ar][ac + 8] = sl1;
        *(uint4*)&sW[wr][wc]      = swh;
        *(uint4*)&sW[BN + wr][wc] = swl;
        __syncthreads();
        if (kt + BKT < K) fetch(kt + BKT);
#pragma unroll
        for (int ks = 0; ks < 2; ks++) {
            uint32_t a[2][2][4], b[2][2][4];
#pragma unroll
            for (int p = 0; p < 2; p++) {
#pragma unroll
                for (int mf = 0; mf < 2; mf++) ldsm4(a[p][mf], a_off[p][mf] + ks * 32);
#pragma unroll
                for (int np = 0; np < 2; np++) ldsm4(b[p][np], b_off[p][np] + ks * 32);
            }
#pragma unroll
            for (int mf = 0; mf < 2; mf++)
#pragma unroll
                for (int nf = 0; nf < 4; nf++) {
                    uint32_t bh0 = b[0][nf >> 1][(nf & 1) * 2], bh1 = b[0][nf >> 1][(nf & 1) * 2 + 1];
                    uint32_t bl0 = b[1][nf >> 1][(nf & 1) * 2], bl1 = b[1][nf >> 1][(nf & 1) * 2 + 1];
                    mma_bf16(acc[mf][nf], a[0][mf], bh0, bh1);
                    mma_bf16(acc[mf][nf], a[0][mf], bl0, bl1);
                    mma_bf16(acc[mf][nf], a[1][mf], bh0, bh1);
                }
        }
    }
}

template <int K1, int K2, bool WF32, bool WHILO>
__global__ __launch_bounds__(256, 2) void gemm_mma(
    const bf16* __restrict__ A1hi, const bf16* __restrict__ A1lo,
    const bf16* __restrict__ A2hi, const bf16* __restrict__ A2lo,
    const bf16* __restrict__ W1hi, const bf16* __restrict__ W1lo,
    const bf16* __restrict__ W2hi, const bf16* __restrict__ W2lo,
    const float* __restrict__ bias,
    float* __restrict__ C, bf16* __restrict__ Ohi, bf16* __restrict__ Olo,
    int M, int N, int hilo_limit) {
    __shared__ bf16 sA[2 * BM][SLDA];
    __shared__ bf16 sW[2 * BN][SLDA];
    float acc[2][4][4];
#pragma unroll
    for (int i = 0; i < 2; i++)
#pragma unroll
        for (int j = 0; j < 4; j++)
#pragma unroll
            for (int k = 0; k < 4; k++) acc[i][j][k] = 0.f;

    int m0 = blockIdx.x * BM, n0 = blockIdx.y * BN;

    mma_phase<K1>(A1hi, A1lo, W1hi, W1lo, M, m0, n0, sA, sW, acc);
    if constexpr (K2 > 0)
        mma_phase<K2>(A2hi, A2lo, W2hi, W2lo, M, m0, n0, sA, sW, acc);

    int t = threadIdx.x, lane = t & 31, warp = t >> 5;
    int wm = (warp & 3) * 32, wn = (warp >> 2) * 32;
#pragma unroll
    for (int mf = 0; mf < 2; mf++) {
        int row0 = m0 + wm + mf * 16 + (lane >> 2);
        int row1 = row0 + 8;
#pragma unroll
        for (int nf = 0; nf < 4; nf++) {
            int col = n0 + wn + nf * 8 + (lane & 3) * 2;
            float b0 = bias[col], b1 = bias[col + 1];
            float v00 = acc[mf][nf][0] + b0, v01 = acc[mf][nf][1] + b1;
            float v10 = acc[mf][nf][2] + b0, v11 = acc[mf][nf][3] + b1;
#pragma unroll
            for (int half = 0; half < 2; half++) {
                int row = half ? row1 : row0;
                float a0 = half ? v10 : v00;
                float a1 = half ? v11 : v01;
                if (row < M) {
                    if (WF32) {
                        *(float2*)&C[(size_t)row * N + col] = make_float2(a0, a1);
                    }
                    if (WHILO && row < hilo_limit) {
                        float r0 = fmaxf(a0, 0.f), r1 = fmaxf(a1, 0.f);
                        bf16 h0, l0, h1, l1;
                        split2(r0, h0, l0); split2(r1, h1, l1);
                        __nv_bfloat162 hv; hv.x = h0; hv.y = h1;
                        __nv_bfloat162 lv; lv.x = l0; lv.y = l1;
                        *(__nv_bfloat162*)&Ohi[(size_t)row * N + col] = hv;
                        *(__nv_bfloat162*)&Olo[(size_t)row * N + col] = lv;
                    }
                }
            }
        }
    }
}

// ---------------- log_softmax ----------------
__global__ void logsoftmax_kernel(const float* __restrict__ logits, float* __restrict__ out) {
    __shared__ float red[128];
    int row = blockIdx.x;
    int t = threadIdx.x;
    float v = logits[row * F_OUT + t];
    red[t] = v;
    __syncthreads();
    for (int off = 64; off > 0; off >>= 1) {
        if (t < off) red[t] = fmaxf(red[t], red[t + off]);
        __syncthreads();
    }
    float mx = red[0];
    __syncthreads();
    red[t] = expf(v - mx);
    __syncthreads();
    for (int off = 64; off > 0; off >>= 1) {
        if (t < off) red[t] += red[t + off];
        __syncthreads();
    }
    float lse = logf(red[0]);
    out[row * F_OUT + t] = v - mx - lse;
}

// ---------------- launch ----------------
extern "C" void kernel_launch(void* const* d_in, const int* in_sizes, int n_in,
                              void* d_out, int out_size) {
    const float* x   = (const float*)d_in[0];
    const int*   ei1 = (const int*)d_in[1];
    const int*   ei2 = (const int*)d_in[2];
    const float* Wl1 = (const float*)d_in[3];
    const float* bl1 = (const float*)d_in[4];
    const float* Wr1 = (const float*)d_in[5];
    const float* Wl2 = (const float*)d_in[6];
    const float* bl2 = (const float*)d_in[7];
    const float* Wr2 = (const float*)d_in[8];
    const float* W1  = (const float*)d_in[9];
    const float* b1  = (const float*)d_in[10];
    const float* W2  = (const float*)d_in[11];
    const float* b2  = (const float*)d_in[12];

    int E1 = in_sizes[1] / 2;
    int E2 = in_sizes[2] / 2;
    const int* src1 = ei1;
    const int* tgt1 = ei1 + E1;
    const int* src2 = ei2;
    const int* tgt2 = ei2 + E2;

    float* out_ls  = (float*)d_out;
    float* out_emb = (float*)d_out + N_TGT2 * F_OUT;

    bf16 *p_m1hi, *p_m1lo, *p_h1hi, *p_h1lo, *p_m2hi, *p_m2lo;
    bf16 *p_h2hi, *p_h2lo, *p_erhi, *p_erlo;
    bf16 *p_wl1h, *p_wl1l, *p_wr1h, *p_wr1l, *p_wl2h, *p_wl2l, *p_wr2h, *p_wr2l;
    bf16 *p_w1h, *p_w1l, *p_w2h, *p_w2l;
    float *p_h1, *p_logits;
    int *p_cnt1, *p_cnt2, *p_bsum1, *p_bsum2, *p_offs1, *p_offs2, *p_csr1, *p_csr2;
    cudaGetSymbolAddress((void**)&p_m1hi, g_m1_hi); cudaGetSymbolAddress((void**)&p_m1lo, g_m1_lo);
    cudaGetSymbolAddress((void**)&p_h1hi, g_h1_hi); cudaGetSymbolAddress((void**)&p_h1lo, g_h1_lo);
    cudaGetSymbolAddress((void**)&p_m2hi, g_m2_hi); cudaGetSymbolAddress((void**)&p_m2lo, g_m2_lo);
    cudaGetSymbolAddress((void**)&p_h2hi, g_h2_hi); cudaGetSymbolAddress((void**)&p_h2lo, g_h2_lo);
    cudaGetSymbolAddress((void**)&p_erhi, g_er_hi); cudaGetSymbolAddress((void**)&p_erlo, g_er_lo);
    cudaGetSymbolAddress((void**)&p_wl1h, g_wl1_hi); cudaGetSymbolAddress((void**)&p_wl1l, g_wl1_lo);
    cudaGetSymbolAddress((void**)&p_wr1h, g_wr1_hi); cudaGetSymbolAddress((void**)&p_wr1l, g_wr1_lo);
    cudaGetSymbolAddress((void**)&p_wl2h, g_wl2_hi); cudaGetSymbolAddress((void**)&p_wl2l, g_wl2_lo);
    cudaGetSymbolAddress((void**)&p_wr2h, g_wr2_hi); cudaGetSymbolAddress((void**)&p_wr2l, g_wr2_lo);
    cudaGetSymbolAddress((void**)&p_w1h,  g_w1_hi);  cudaGetSymbolAddress((void**)&p_w1l,  g_w1_lo);
    cudaGetSymbolAddress((void**)&p_w2h,  g_w2_hi);  cudaGetSymbolAddress((void**)&p_w2l,  g_w2_lo);
    cudaGetSymbolAddress((void**)&p_h1,     g_h1);
    cudaGetSymbolAddress((void**)&p_logits, g_logits);
    cudaGetSymbolAddress((void**)&p_cnt1,  g_cnt1);
    cudaGetSymbolAddress((void**)&p_cnt2,  g_cnt2);
    cudaGetSymbolAddress((void**)&p_bsum1, g_bsum1);
    cudaGetSymbolAddress((void**)&p_bsum2, g_bsum2);
    cudaGetSymbolAddress((void**)&p_offs1, g_offs1);
    cudaGetSymbolAddress((void**)&p_offs2, g_offs2);
    cudaGetSymbolAddress((void**)&p_csr1,  g_csr1);
    cudaGetSymbolAddress((void**)&p_csr2,  g_csr2);

    const int G1 = (N_TGT1 + SCAN_B - 1) / SCAN_B;
    const int G2 = (N_TGT2 + SCAN_B - 1) / SCAN_B;

    cudaFuncSetAttribute(gemm1_n192, cudaFuncAttributeMaxDynamicSharedMemorySize, G1_SMEM_BYTES);

    // weight splits
    {
        const int total = 2 * (F_HID * F_IN) + 3 * (F_HID * F_HID) + F_OUT * F_HID;
        split_weights_kernel<<<(total + 255) / 256, 256>>>(Wl1, Wr1, Wl2, Wr2, W1, W2);
    }

    // ---- both layers' CSR builds, merged ----
    cudaMemsetAsync(p_cnt1, 0, N_TGT1 * sizeof(int));
    cudaMemsetAsync(p_cnt2, 0, N_TGT2 * sizeof(int));
    hist2_kernel<<<(E1 + E2 + 255) / 256, 256>>>(tgt1, E1, p_cnt1, tgt2, E2, p_cnt2);
    block_sum2_kernel<<<G1 + G2, SCAN_B>>>(p_cnt1, N_TGT1, p_bsum1, G1, p_cnt2, N_TGT2, p_bsum2);
    scan2_kernel<<<2, 256>>>(p_bsum1, G1, p_offs1 + N_TGT1, p_bsum2, G2, p_offs2 + N_TGT2);
    scatter2_kernel<<<G1 + G2, SCAN_B>>>(p_cnt1, N_TGT1, p_bsum1, G1, p_offs1, p_cnt1,
                                         p_cnt2, N_TGT2, p_bsum2, p_offs2, p_cnt2);
    fill2_kernel<<<(E1 + E2 + 255) / 256, 256>>>(src1, tgt1, E1, p_cnt1, p_csr1,
                                                 src2, tgt2, E2, p_cnt2, p_csr2);

    // ---- layer-1 aggregate: two half-feature passes ----
    aggregate_half<F_IN, 128><<<N_TGT1, 128>>>(x, p_csr1, p_offs1, p_m1hi, p_m1lo, 0);
    aggregate_half<F_IN, 128><<<N_TGT1, 128>>>(x, p_csr1, p_offs1, p_m1hi, p_m1lo, 128);

    // ---- h1 = relu(mean1 @ Wl1^T + x @ Wr1^T + bl1): full-N gemm ----
    gemm1_n192<<<(N_TGT1 + G1BM - 1) / G1BM, 256, G1_SMEM_BYTES>>>(
        p_m1hi, p_m1lo, x, p_wl1h, p_wl1l, p_wr1h, p_wr1l,
        bl1, p_h1, p_h1hi, p_h1lo, N_TGT1, N_TGT2);

    // ---- layer-2 aggregate ----
    aggregate_hilo<F_HID><<<N_TGT2, F_HID>>>(p_h1, p_csr2, p_offs2, p_m2hi, p_m2lo);

    // h2 = relu(mean2 @ Wl2^T + h1[:10k] @ Wr2^T + bl2)
    gemm_mma<F_HID, F_HID, false, true>
        <<<dim3((N_TGT2 + BM - 1) / BM, F_HID / BN), 256>>>(
            p_m2hi, p_m2lo, p_h1hi, p_h1lo, p_wl2h, p_wl2l, p_wr2h, p_wr2l,
            bl2, nullptr, p_h2hi, p_h2lo, N_TGT2, F_HID, N_TGT2);

    // embedding = h2 @ W1^T + b1
    gemm_mma<F_HID, 0, true, true>
        <<<dim3((N_TGT2 + BM - 1) / BM, F_HID / BN), 256>>>(
            p_h2hi, p_h2lo, nullptr, nullptr, p_w1h, p_w1l, nullptr, nullptr,
            b1, out_emb, p_erhi, p_erlo, N_TGT2, F_HID, N_TGT2);

    // logits = relu(emb) @ W2^T + b2
    gemm_mma<F_HID, 0, true, false>
        <<<dim3((N_TGT2 + BM - 1) / BM, F_OUT / BN), 256>>>(
            p_erhi, p_erlo, nullptr, nullptr, p_w2h, p_w2l, nullptr, nullptr,
            b2, p_logits, nullptr, nullptr, N_TGT2, F_OUT, 0);

    logsoftmax_kernel<<<N_TGT2, F_OUT>>>(p_logits, out_ls);
}